// round 1
// baseline (speedup 1.0000x reference)
#include <cuda_runtime.h>
#include <math.h>
#include <float.h>

#define BATCH 8
#define CH 64
#define NPTS 4096
#define KNN 20
#define OC 64
#define NPOINTS (BATCH * NPTS)          // 32768
#define NEG_SLOPE 0.2f
#define BN_EPS 1e-5f

// ---------------- scratch (static device globals; no allocation) ------------
__device__ float g_D[(size_t)BATCH * NPTS * NPTS];   // 536 MB keys: 2*inner - |x_m|^2
__device__ int   g_idx[NPOINTS * KNN];
__device__ float g_u[NPOINTS * OC];                  // point-major, channel-last
__device__ float g_v[NPOINTS * OC];
__device__ float g_sq[NPOINTS];
__device__ float g_Mmax[NPOINTS * OC];
__device__ float g_Mmin[NPOINTS * OC];
__device__ float g_partS[8192 * OC];
__device__ float g_partQ[8192 * OC];
__device__ float g_sum[OC];
__device__ float g_sumsq[OC];
__device__ float g_scale[OC];
__device__ float g_shift[OC];

// ---------------- |x|^2 per point -------------------------------------------
__global__ void sq_kernel(const float* __restrict__ x) {
    int t = blockIdx.x * blockDim.x + threadIdx.x;   // 0..32767
    int b = t >> 12, n = t & (NPTS - 1);
    const float* xb = x + (size_t)b * CH * NPTS + n;
    float s = 0.f;
#pragma unroll
    for (int c = 0; c < CH; c++) { float v = xb[(size_t)c * NPTS]; s = fmaf(v, v, s); }
    g_sq[t] = s;
}

// ---------------- u = W1*x, v = (W2-W1)*x (channel-last) --------------------
__global__ void __launch_bounds__(256) uv_kernel(const float* __restrict__ x,
                                                 const float* __restrict__ W) {
    __shared__ float Ws[OC][129];       // [o][c], c in [0,128)
    __shared__ float xs[4][CH];
    int tid = threadIdx.x;
    for (int t = tid; t < OC * 2 * CH; t += 256) {
        int o = t >> 7, c = t & 127;
        Ws[o][c] = W[t];
    }
    int p4 = blockIdx.x * 4;            // 4 points per block (same batch: 4096%4==0)
    int b = p4 >> 12, n0 = p4 & (NPTS - 1);
    for (int t = tid; t < 4 * CH; t += 256) {
        int c = t >> 2, p = t & 3;
        xs[p][c] = x[(size_t)b * CH * NPTS + (size_t)c * NPTS + n0 + p];
    }
    __syncthreads();
    int o = tid & 63, p = tid >> 6;
    float u = 0.f, v = 0.f;
#pragma unroll
    for (int c = 0; c < CH; c++) {
        float xv = xs[p][c];
        float w1 = Ws[o][c], w2 = Ws[o][CH + c];
        u = fmaf(w1, xv, u);
        v = fmaf(w2 - w1, xv, v);
    }
    size_t base = (size_t)(p4 + p) * OC + o;
    g_u[base] = u;
    g_v[base] = v;
}

// ---------------- distance keys: key = 2*x_n.x_m - |x_m|^2 (maximize) -------
__global__ void __launch_bounds__(256) dist_kernel(const float* __restrict__ x) {
    __shared__ float As[32][128];
    __shared__ float Bs[32][128];
    __shared__ float sqs[128];
    int b = blockIdx.z;
    int n0 = blockIdx.y << 7, m0 = blockIdx.x << 7;
    const float* xb = x + (size_t)b * CH * NPTS;
    int tid = threadIdx.x;
    if (tid < 128) sqs[tid] = g_sq[(b << 12) + m0 + tid];

    float acc[8][8];
#pragma unroll
    for (int i = 0; i < 8; i++)
#pragma unroll
        for (int j = 0; j < 8; j++) acc[i][j] = 0.f;

    int tx = tid & 15, ty = tid >> 4;

    for (int ks = 0; ks < CH; ks += 32) {
        __syncthreads();
        for (int t = tid; t < 32 * 128; t += 256) {
            int c = t >> 7, i = t & 127;
            As[c][i] = xb[(size_t)(ks + c) * NPTS + n0 + i];
            Bs[c][i] = xb[(size_t)(ks + c) * NPTS + m0 + i];
        }
        __syncthreads();
#pragma unroll
        for (int k = 0; k < 32; k++) {
            float a[8], bv[8];
#pragma unroll
            for (int i = 0; i < 8; i++) a[i] = As[k][ty * 8 + i];
#pragma unroll
            for (int j = 0; j < 8; j++) bv[j] = Bs[k][tx * 8 + j];
#pragma unroll
            for (int i = 0; i < 8; i++)
#pragma unroll
                for (int j = 0; j < 8; j++) acc[i][j] = fmaf(a[i], bv[j], acc[i][j]);
        }
    }

    float* Dp = g_D + ((size_t)b << 24) + (size_t)n0 * NPTS + m0;
#pragma unroll
    for (int i = 0; i < 8; i++) {
        int row = ty * 8 + i;
#pragma unroll
        for (int j = 0; j < 8; j += 4) {
            float4 v4;
            v4.x = 2.f * acc[i][j + 0] - sqs[tx * 8 + j + 0];
            v4.y = 2.f * acc[i][j + 1] - sqs[tx * 8 + j + 1];
            v4.z = 2.f * acc[i][j + 2] - sqs[tx * 8 + j + 2];
            v4.w = 2.f * acc[i][j + 3] - sqs[tx * 8 + j + 3];
            *(float4*)(Dp + (size_t)row * NPTS + tx * 8 + j) = v4;
        }
    }
}

// ---------------- top-20 per row (largest keys, lower-index tie-break) ------
__global__ void __launch_bounds__(128) select_kernel() {
    __shared__ float sd[4][32 * KNN];
    __shared__ int   si[4][32 * KNN];
    int w = threadIdx.x >> 5, lane = threadIdx.x & 31;
    int rowi = blockIdx.x * 4 + w;                    // 0..32767 (== b*4096+n)
    const float* row = g_D + (size_t)rowi * NPTS;

    float best[KNN];
    int   bidx[KNN];
#pragma unroll
    for (int t = 0; t < KNN; t++) { best[t] = -FLT_MAX; bidx[t] = -1; }
    float worst = -FLT_MAX;
    int wp = 0;

    for (int j = lane; j < NPTS; j += 32) {
        float d = row[j];
        if (d > worst) {                               // strict: keeps lowest index on ties
            best[wp] = d; bidx[wp] = j;
            worst = best[0]; wp = 0;
#pragma unroll
            for (int t = 1; t < KNN; t++)
                if (best[t] < worst) { worst = best[t]; wp = t; }
        }
    }

#pragma unroll
    for (int t = 0; t < KNN; t++) {
        sd[w][lane * KNN + t] = best[t];
        si[w][lane * KNN + t] = bidx[t];
    }
    __syncwarp();

    int* outp = g_idx + (size_t)rowi * KNN;
    for (int r = 0; r < KNN; r++) {
        float bd = -FLT_MAX;
        int bi = 0x7fffffff, bp = -1;
#pragma unroll
        for (int t = 0; t < KNN; t++) {
            int slot = lane * KNN + t;
            float d = sd[w][slot];
            int ii = si[w][slot];
            if (d > bd || (d == bd && ii < bi)) { bd = d; bi = ii; bp = slot; }
        }
#pragma unroll
        for (int off = 16; off > 0; off >>= 1) {
            float od = __shfl_down_sync(0xffffffffu, bd, off);
            int   oi = __shfl_down_sync(0xffffffffu, bi, off);
            int   op = __shfl_down_sync(0xffffffffu, bp, off);
            if (od > bd || (od == bd && oi < bi)) { bd = od; bi = oi; bp = op; }
        }
        bp = __shfl_sync(0xffffffffu, bp, 0);
        bi = __shfl_sync(0xffffffffu, bi, 0);
        if (lane == 0) outp[r] = bi;
        if (lane == bp / KNN) sd[w][bp] = -FLT_MAX;    // owner invalidates
        __syncwarp();
    }
}

// ---------------- gather u over neighbors: max/min/sum/sumsq + BN partials --
__global__ void __launch_bounds__(256) gather_kernel() {
    __shared__ float shS[4][OC];
    __shared__ float shQ[4][OC];
    int o = threadIdx.x & 63, p = threadIdx.x >> 6;
    int pt = blockIdx.x * 4 + p;                      // point id 0..32767
    int b = pt >> 12;
    const int* idxp = g_idx + (size_t)pt * KNN;
    const float* ub = g_u + ((size_t)(b << 12)) * OC;

    float mx = -FLT_MAX, mn = FLT_MAX, s = 0.f, q = 0.f;
#pragma unroll
    for (int k = 0; k < KNN; k++) {
        int j = idxp[k];
        float uv = ub[(size_t)j * OC + o];
        mx = fmaxf(mx, uv);
        mn = fminf(mn, uv);
        s += uv;
        q = fmaf(uv, uv, q);
    }
    size_t base = (size_t)pt * OC + o;
    float vv = g_v[base];
    g_Mmax[base] = mx;
    g_Mmin[base] = mn;
    shS[p][o] = s + (float)KNN * vv;
    shQ[p][o] = q + 2.f * vv * s + (float)KNN * vv * vv;
    __syncthreads();
    if (p == 0) {
        g_partS[blockIdx.x * OC + o] = shS[0][o] + shS[1][o] + shS[2][o] + shS[3][o];
        g_partQ[blockIdx.x * OC + o] = shQ[0][o] + shQ[1][o] + shQ[2][o] + shQ[3][o];
    }
}

// ---------------- deterministic per-channel reduction ------------------------
__global__ void reduce_kernel() {
    __shared__ float sh[256];
    int o = blockIdx.x & 63;
    bool isQ = (blockIdx.x & 64) != 0;
    const float* src = isQ ? g_partQ : g_partS;
    float s = 0.f;
    for (int i = threadIdx.x; i < 8192; i += 256) s += src[(size_t)i * OC + o];
    sh[threadIdx.x] = s;
    __syncthreads();
    for (int st = 128; st > 0; st >>= 1) {
        if (threadIdx.x < st) sh[threadIdx.x] += sh[threadIdx.x + st];
        __syncthreads();
    }
    if (threadIdx.x == 0) {
        if (isQ) g_sumsq[o] = sh[0]; else g_sum[o] = sh[0];
    }
}

__global__ void finalize_kernel(const float* __restrict__ gamma,
                                const float* __restrict__ beta) {
    int o = threadIdx.x;
    float cnt = (float)((size_t)BATCH * NPTS * KNN);  // 655360
    float mean = g_sum[o] / cnt;
    float var = g_sumsq[o] / cnt - mean * mean;
    float sc = gamma[o] * rsqrtf(var + BN_EPS);
    g_scale[o] = sc;
    g_shift[o] = beta[o] - mean * sc;
}

// ---------------- output: scale/shift/leaky + transpose to [B, O, N] --------
__global__ void __launch_bounds__(256) out_kernel(float* __restrict__ out) {
    __shared__ float tile[OC][33];
    int b = blockIdx.y;
    int n0 = blockIdx.x * 32;
    for (int t = threadIdx.x; t < OC * 32; t += 256) {
        int nl = t >> 6, o = t & 63;
        size_t base = ((size_t)((b << 12) + n0 + nl)) * OC + o;
        float sc = g_scale[o];
        float m = (sc >= 0.f) ? g_Mmax[base] : g_Mmin[base];
        float y = fmaf(sc, m + g_v[base], g_shift[o]);
        tile[o][nl] = (y >= 0.f) ? y : NEG_SLOPE * y;
    }
    __syncthreads();
    for (int t = threadIdx.x; t < OC * 32; t += 256) {
        int o = t >> 5, nl = t & 31;
        out[((size_t)b * OC + o) * NPTS + n0 + nl] = tile[o][nl];
    }
}

// ---------------- launch ------------------------------------------------------
extern "C" void kernel_launch(void* const* d_in, const int* in_sizes, int n_in,
                              void* d_out, int out_size) {
    const float* x     = (const float*)d_in[0];   // [8, 64, 4096]
    const float* W     = (const float*)d_in[1];   // [64, 128]
    const float* gamma = (const float*)d_in[2];   // [64]
    const float* beta  = (const float*)d_in[3];   // [64]
    float* out = (float*)d_out;                   // [8, 64, 4096]

    sq_kernel<<<NPOINTS / 256, 256>>>(x);
    uv_kernel<<<NPOINTS / 4, 256>>>(x, W);
    dist_kernel<<<dim3(NPTS / 128, NPTS / 128, BATCH), 256>>>(x);
    select_kernel<<<NPOINTS / 4, 128>>>();
    gather_kernel<<<NPOINTS / 4, 256>>>();
    reduce_kernel<<<128, 256>>>();
    finalize_kernel<<<1, 64>>>(gamma, beta);
    out_kernel<<<dim3(NPTS / 32, BATCH), 256>>>(out);
}

// round 2
// speedup vs baseline: 1.3896x; 1.3896x over previous
#include <cuda_runtime.h>
#include <math.h>
#include <float.h>

#define BATCH 8
#define CH 64
#define NPTS 4096
#define KNN 20
#define OC 64
#define NPOINTS (BATCH * NPTS)          // 32768
#define NEG_SLOPE 0.2f
#define BN_EPS 1e-5f

#define BM 128
#define KEYP 130                        // padded key row (floats)

// ---------------- scratch (static device globals; no allocation) ------------
__device__ int   g_idx[NPOINTS * KNN];
__device__ float g_u[NPOINTS * OC];                  // point-major, channel-last
__device__ float g_v[NPOINTS * OC];
__device__ float g_sq[NPOINTS];
__device__ float g_Mmax[NPOINTS * OC];
__device__ float g_Mmin[NPOINTS * OC];
__device__ float g_partS[8192 * OC];
__device__ float g_partQ[8192 * OC];
__device__ float g_sum[OC];
__device__ float g_sumsq[OC];
__device__ float g_scale[OC];
__device__ float g_shift[OC];

// ---------------- f32x2 helpers ----------------------------------------------
__device__ __forceinline__ unsigned long long ffma2(unsigned long long a,
                                                    unsigned long long b,
                                                    unsigned long long c) {
    unsigned long long d;
    asm("fma.rn.f32x2 %0, %1, %2, %3;" : "=l"(d) : "l"(a), "l"(b), "l"(c));
    return d;
}
__device__ __forceinline__ unsigned long long dup2(float v) {
    unsigned long long d;
    asm("mov.b64 %0, {%1, %1};" : "=l"(d) : "f"(v));
    return d;
}
__device__ __forceinline__ void unpack2(unsigned long long p, float& lo, float& hi) {
    asm("mov.b64 {%0, %1}, %2;" : "=f"(lo), "=f"(hi) : "l"(p));
}

// ---------------- |x|^2 per point -------------------------------------------
__global__ void sq_kernel(const float* __restrict__ x) {
    int t = blockIdx.x * blockDim.x + threadIdx.x;   // 0..32767
    int b = t >> 12, n = t & (NPTS - 1);
    const float* xb = x + (size_t)b * CH * NPTS + n;
    float s = 0.f;
#pragma unroll
    for (int c = 0; c < CH; c++) { float v = xb[(size_t)c * NPTS]; s = fmaf(v, v, s); }
    g_sq[t] = s;
}

// ---------------- u = W1*x, v = (W2-W1)*x (channel-last) --------------------
__global__ void __launch_bounds__(256) uv_kernel(const float* __restrict__ x,
                                                 const float* __restrict__ W) {
    __shared__ float Ws[OC][129];
    __shared__ float xs[4][CH];
    int tid = threadIdx.x;
    for (int t = tid; t < OC * 2 * CH; t += 256) {
        int o = t >> 7, c = t & 127;
        Ws[o][c] = W[t];
    }
    int p4 = blockIdx.x * 4;
    int b = p4 >> 12, n0 = p4 & (NPTS - 1);
    for (int t = tid; t < 4 * CH; t += 256) {
        int c = t >> 2, p = t & 3;
        xs[p][c] = x[(size_t)b * CH * NPTS + (size_t)c * NPTS + n0 + p];
    }
    __syncthreads();
    int o = tid & 63, p = tid >> 6;
    float u = 0.f, v = 0.f;
#pragma unroll
    for (int c = 0; c < CH; c++) {
        float xv = xs[p][c];
        float w1 = Ws[o][c], w2 = Ws[o][CH + c];
        u = fmaf(w1, xv, u);
        v = fmaf(w2 - w1, xv, v);
    }
    size_t base = (size_t)(p4 + p) * OC + o;
    g_u[base] = u;
    g_v[base] = v;
}

// ---------------- fused distance GEMM + top-20 selection --------------------
// Block: 128 rows (n) of one batch; loops over all 32 m-tiles of 128.
// keys = 2*x_n.x_m - |x_m|^2 (maximize). Selection: 1 owner thread per row,
// SMEM top-20 list, worst/wp cached in registers.
__global__ void __launch_bounds__(256, 1) fused_knn_kernel(const float* __restrict__ x) {
    extern __shared__ float sm[];
    float* As    = sm;                     // [64][128]
    float* Bs    = As + 64 * 128;          // [64][128]
    float* keys  = Bs + 64 * 128;          // [128][KEYP]
    float* sqs   = keys + 128 * KEYP;      // [128]
    float* rbest = sqs + 128;              // [128][21]
    int*   ridx  = (int*)(rbest + 128 * 21); // [128][21]

    int b = blockIdx.y;
    int n0 = blockIdx.x * BM;
    const float* xb = x + (size_t)b * CH * NPTS;
    int tid = threadIdx.x;
    int tx = tid & 15, ty = tid >> 4;

    // load A tile once (k-major)
    for (int t = tid; t < 64 * 128; t += 256) {
        int c = t >> 7, i = t & 127;
        As[c * 128 + i] = xb[(size_t)c * NPTS + n0 + i];
    }
    for (int t = tid; t < 128 * 21; t += 256) { rbest[t] = -FLT_MAX; ridx[t] = -1; }

    // per-owner selection state (only meaningful for tid < 128)
    float worst = -FLT_MAX;
    int wp = 0;
    int rb = (tid & 127) * 21;

    for (int mt = 0; mt < 32; mt++) {
        int m0 = mt * 128;
        __syncthreads();   // prev selection done; Bs/keys reusable
        for (int t = tid; t < 64 * 128; t += 256) {
            int c = t >> 7, i = t & 127;
            Bs[c * 128 + i] = xb[(size_t)c * NPTS + m0 + i];
        }
        if (tid < 128) sqs[tid] = g_sq[(b << 12) + m0 + tid];
        __syncthreads();   // Bs ready

        // ---- GEMM: rows ty*8..+7, cols {tx*4..+3} and {64+tx*4..+3}
        unsigned long long acc[8][4];
#pragma unroll
        for (int i = 0; i < 8; i++)
#pragma unroll
            for (int j = 0; j < 4; j++) acc[i][j] = 0ull;

#pragma unroll 4
        for (int k = 0; k < 64; k++) {
            const float* ak = As + k * 128 + ty * 8;
            float4 af0 = *(const float4*)ak;
            float4 af1 = *(const float4*)(ak + 4);
            unsigned long long a2[8];
            a2[0] = dup2(af0.x); a2[1] = dup2(af0.y);
            a2[2] = dup2(af0.z); a2[3] = dup2(af0.w);
            a2[4] = dup2(af1.x); a2[5] = dup2(af1.y);
            a2[6] = dup2(af1.z); a2[7] = dup2(af1.w);
            const unsigned long long* bp0 = (const unsigned long long*)(Bs + k * 128 + tx * 4);
            const unsigned long long* bp1 = (const unsigned long long*)(Bs + k * 128 + 64 + tx * 4);
            unsigned long long b2[4];
            b2[0] = bp0[0]; b2[1] = bp0[1];
            b2[2] = bp1[0]; b2[3] = bp1[1];
#pragma unroll
            for (int i = 0; i < 8; i++)
#pragma unroll
                for (int j = 0; j < 4; j++)
                    acc[i][j] = ffma2(a2[i], b2[j], acc[i][j]);
        }

        // ---- key transform + SMEM store
#pragma unroll
        for (int i = 0; i < 8; i++) {
            int row = ty * 8 + i;
            float* kr = keys + row * KEYP;
#pragma unroll
            for (int j = 0; j < 4; j++) {
                int cb = (j < 2) ? (tx * 4 + 2 * j) : (64 + tx * 4 + 2 * (j - 2));
                float lo, hi;
                unpack2(acc[i][j], lo, hi);
                float2 kv;
                kv.x = fmaf(2.f, lo, -sqs[cb]);
                kv.y = fmaf(2.f, hi, -sqs[cb + 1]);
                *(float2*)(kr + cb) = kv;
            }
        }
        __syncthreads();   // keys ready

        // ---- selection: owner thread per row
        if (tid < 128) {
            const float2* krow = (const float2*)(keys + tid * KEYP);
#pragma unroll 4
            for (int c2 = 0; c2 < 64; c2++) {
                float2 kk = krow[c2];
                if (kk.x > worst) {
                    rbest[rb + wp] = kk.x; ridx[rb + wp] = m0 + 2 * c2;
                    worst = rbest[rb]; wp = 0;
#pragma unroll
                    for (int t = 1; t < KNN; t++) {
                        float v = rbest[rb + t];
                        if (v < worst) { worst = v; wp = t; }
                    }
                }
                if (kk.y > worst) {
                    rbest[rb + wp] = kk.y; ridx[rb + wp] = m0 + 2 * c2 + 1;
                    worst = rbest[rb]; wp = 0;
#pragma unroll
                    for (int t = 1; t < KNN; t++) {
                        float v = rbest[rb + t];
                        if (v < worst) { worst = v; wp = t; }
                    }
                }
            }
        }
    }
    __syncthreads();

    if (tid < 128) {
        int* outp = g_idx + (size_t)((b << 12) + n0 + tid) * KNN;
#pragma unroll
        for (int t = 0; t < KNN; t++) outp[t] = ridx[rb + t];
    }
}

// ---------------- gather u over neighbors: max/min + BN partials ------------
__global__ void __launch_bounds__(256) gather_kernel() {
    __shared__ float shS[4][OC];
    __shared__ float shQ[4][OC];
    int o = threadIdx.x & 63, p = threadIdx.x >> 6;
    int pt = blockIdx.x * 4 + p;
    int b = pt >> 12;
    const int* idxp = g_idx + (size_t)pt * KNN;
    const float* ub = g_u + ((size_t)(b << 12)) * OC;

    float mx = -FLT_MAX, mn = FLT_MAX, s = 0.f, q = 0.f;
#pragma unroll
    for (int k = 0; k < KNN; k++) {
        int j = idxp[k];
        float uv = ub[(size_t)j * OC + o];
        mx = fmaxf(mx, uv);
        mn = fminf(mn, uv);
        s += uv;
        q = fmaf(uv, uv, q);
    }
    size_t base = (size_t)pt * OC + o;
    float vv = g_v[base];
    g_Mmax[base] = mx;
    g_Mmin[base] = mn;
    shS[p][o] = s + (float)KNN * vv;
    shQ[p][o] = q + 2.f * vv * s + (float)KNN * vv * vv;
    __syncthreads();
    if (p == 0) {
        g_partS[blockIdx.x * OC + o] = shS[0][o] + shS[1][o] + shS[2][o] + shS[3][o];
        g_partQ[blockIdx.x * OC + o] = shQ[0][o] + shQ[1][o] + shQ[2][o] + shQ[3][o];
    }
}

// ---------------- deterministic per-channel reduction ------------------------
__global__ void reduce_kernel() {
    __shared__ float sh[256];
    int o = blockIdx.x & 63;
    bool isQ = (blockIdx.x & 64) != 0;
    const float* src = isQ ? g_partQ : g_partS;
    float s = 0.f;
    for (int i = threadIdx.x; i < 8192; i += 256) s += src[(size_t)i * OC + o];
    sh[threadIdx.x] = s;
    __syncthreads();
    for (int st = 128; st > 0; st >>= 1) {
        if (threadIdx.x < st) sh[threadIdx.x] += sh[threadIdx.x + st];
        __syncthreads();
    }
    if (threadIdx.x == 0) {
        if (isQ) g_sumsq[o] = sh[0]; else g_sum[o] = sh[0];
    }
}

__global__ void finalize_kernel(const float* __restrict__ gamma,
                                const float* __restrict__ beta) {
    int o = threadIdx.x;
    float cnt = (float)((size_t)BATCH * NPTS * KNN);
    float mean = g_sum[o] / cnt;
    float var = g_sumsq[o] / cnt - mean * mean;
    float sc = gamma[o] * rsqrtf(var + BN_EPS);
    g_scale[o] = sc;
    g_shift[o] = beta[o] - mean * sc;
}

// ---------------- output: scale/shift/leaky + transpose to [B, O, N] --------
__global__ void __launch_bounds__(256) out_kernel(float* __restrict__ out) {
    __shared__ float tile[OC][33];
    int b = blockIdx.y;
    int n0 = blockIdx.x * 32;
    for (int t = threadIdx.x; t < OC * 32; t += 256) {
        int nl = t >> 6, o = t & 63;
        size_t base = ((size_t)((b << 12) + n0 + nl)) * OC + o;
        float sc = g_scale[o];
        float m = (sc >= 0.f) ? g_Mmax[base] : g_Mmin[base];
        float y = fmaf(sc, m + g_v[base], g_shift[o]);
        tile[o][nl] = (y >= 0.f) ? y : NEG_SLOPE * y;
    }
    __syncthreads();
    for (int t = threadIdx.x; t < OC * 32; t += 256) {
        int o = t >> 5, nl = t & 31;
        out[((size_t)b * OC + o) * NPTS + n0 + nl] = tile[o][nl];
    }
}

// ---------------- launch ------------------------------------------------------
extern "C" void kernel_launch(void* const* d_in, const int* in_sizes, int n_in,
                              void* d_out, int out_size) {
    const float* x     = (const float*)d_in[0];   // [8, 64, 4096]
    const float* W     = (const float*)d_in[1];   // [64, 128]
    const float* gamma = (const float*)d_in[2];   // [64]
    const float* beta  = (const float*)d_in[3];   // [64]
    float* out = (float*)d_out;                   // [8, 64, 4096]

    const int smem_bytes = (64 * 128 + 64 * 128 + 128 * KEYP + 128 + 128 * 21) * 4
                         + 128 * 21 * 4;          // 154112 B
    cudaFuncSetAttribute(fused_knn_kernel,
                         cudaFuncAttributeMaxDynamicSharedMemorySize, smem_bytes);

    sq_kernel<<<NPOINTS / 256, 256>>>(x);
    uv_kernel<<<NPOINTS / 4, 256>>>(x, W);
    fused_knn_kernel<<<dim3(NPTS / BM, BATCH), 256, smem_bytes>>>(x);
    gather_kernel<<<NPOINTS / 4, 256>>>();
    reduce_kernel<<<128, 256>>>();
    finalize_kernel<<<1, 64>>>(gamma, beta);
    out_kernel<<<dim3(NPTS / 32, BATCH), 256>>>(out);
}

// round 4
// speedup vs baseline: 1.6543x; 1.1905x over previous
#include <cuda_runtime.h>
#include <math.h>
#include <float.h>
#include <stdint.h>

#define BATCH 8
#define CH 64
#define NPTS 4096
#define KNN 20
#define OC 64
#define NPOINTS (BATCH * NPTS)          // 32768
#define NEG_SLOPE 0.2f
#define BN_EPS 1e-5f

// ---------------- scratch (static device globals; no allocation) ------------
__device__ int   g_idx[NPOINTS * KNN];
__device__ float g_u[NPOINTS * OC];
__device__ float g_v[NPOINTS * OC];
__device__ float g_sq[NPOINTS];
__device__ float g_Mmax[NPOINTS * OC];
__device__ float g_Mmin[NPOINTS * OC];
__device__ float g_partS[8192 * OC];
__device__ float g_partQ[8192 * OC];
__device__ float g_sum[OC];
__device__ float g_sumsq[OC];
__device__ float g_scale[OC];
__device__ float g_shift[OC];

// ---------------- SMEM layout (float indices into dynamic smem) -------------
#define SM_BPH   0            // 8 kstep x 16 colt x 32 lane x float2 = 8192 f
#define SM_BPM   8192         // 8192 f
#define SM_KEYS  16384        // keys: 128 rows x pitch 130 ; staging: pitch 132
#define SM_HSQ   33280        // 4096 f  (0.5*|x_m|^2 for whole batch row range)
#define SM_RBEST 37376        // 128 x 21
#define SM_RIDX  40064        // 128 x 21 (int)
#define SM_FLOATS 42752
#define SMEM_BYTES (SM_FLOATS * 4)   // 171008 B

#define KEYP 130
#define STGP 132

// ---------------- helpers -----------------------------------------------------
__device__ __forceinline__ float tf32_rna(float v) {
    uint32_t r; asm("cvt.rna.tf32.f32 %0, %1;" : "=r"(r) : "f"(v));
    return __uint_as_float(r);
}
__device__ __forceinline__ void mma_tf32(float* d, const uint32_t* a, uint32_t b0, uint32_t b1) {
    asm volatile(
        "mma.sync.aligned.m16n8k8.row.col.f32.tf32.tf32.f32 "
        "{%0,%1,%2,%3}, {%4,%5,%6,%7}, {%8,%9}, {%0,%1,%2,%3};"
        : "+f"(d[0]), "+f"(d[1]), "+f"(d[2]), "+f"(d[3])
        : "r"(a[0]), "r"(a[1]), "r"(a[2]), "r"(a[3]), "r"(b0), "r"(b1));
}

// ---------------- |x|^2 per point -------------------------------------------
__global__ void sq_kernel(const float* __restrict__ x) {
    int t = blockIdx.x * blockDim.x + threadIdx.x;
    int b = t >> 12, n = t & (NPTS - 1);
    const float* xb = x + (size_t)b * CH * NPTS + n;
    float s = 0.f;
#pragma unroll
    for (int c = 0; c < CH; c++) { float v = xb[(size_t)c * NPTS]; s = fmaf(v, v, s); }
    g_sq[t] = s;
}

// ---------------- u = W1*x, v = (W2-W1)*x (channel-last) --------------------
__global__ void __launch_bounds__(256) uv_kernel(const float* __restrict__ x,
                                                 const float* __restrict__ W) {
    __shared__ float Ws[OC][129];
    __shared__ float xs[4][CH];
    int tid = threadIdx.x;
    for (int t = tid; t < OC * 2 * CH; t += 256) {
        int o = t >> 7, c = t & 127;
        Ws[o][c] = W[t];
    }
    int p4 = blockIdx.x * 4;
    int b = p4 >> 12, n0 = p4 & (NPTS - 1);
    for (int t = tid; t < 4 * CH; t += 256) {
        int c = t >> 2, p = t & 3;
        xs[p][c] = x[(size_t)b * CH * NPTS + (size_t)c * NPTS + n0 + p];
    }
    __syncthreads();
    int o = tid & 63, p = tid >> 6;
    float u = 0.f, v = 0.f;
#pragma unroll
    for (int c = 0; c < CH; c++) {
        float xv = xs[p][c];
        float w1 = Ws[o][c], w2 = Ws[o][CH + c];
        u = fmaf(w1, xv, u);
        v = fmaf(w2 - w1, xv, v);
    }
    size_t base = (size_t)(p4 + p) * OC + o;
    g_u[base] = u;
    g_v[base] = v;
}

// ---------------- fused tf32-split mma.sync distance GEMM + top-20 ----------
__global__ void __launch_bounds__(256, 1) fused_knn_mma(const float* __restrict__ x) {
    extern __shared__ float sm[];
    int* smi = (int*)sm;

    int tid = threadIdx.x;
    int w = tid >> 5, lane = tid & 31;
    int g = lane >> 2, tg = lane & 3;
    int b = blockIdx.y, n0 = blockIdx.x << 7;
    const float* xb = x + (size_t)b * CH * NPTS;

    // ---- halfsq for the whole batch (4096 floats)
    for (int t = tid; t < NPTS; t += 256) sm[SM_HSQ + t] = 0.5f * g_sq[(b << 12) + t];
    // ---- rbest init
    for (int t = tid; t < 128 * 21; t += 256) { sm[SM_RBEST + t] = -FLT_MAX; smi[SM_RIDX + t] = -1; }

    // ---- stage A tile (split h/m) into keys region, pitch STGP
    {
        const float* src = xb + n0;
#pragma unroll
        for (int it = 0; it < 8; it++) {
            int c = it * 8 + w;
            int nn = lane << 2;
            float4 v = *(const float4*)(src + (size_t)c * NPTS + nn);
            float h0 = tf32_rna(v.x), h1 = tf32_rna(v.y), h2 = tf32_rna(v.z), h3 = tf32_rna(v.w);
            float* sh = sm + SM_KEYS + c * STGP + nn;
            float* sl = sh + 64 * STGP;
            sh[0] = h0; sh[1] = h1; sh[2] = h2; sh[3] = h3;
            sl[0] = tf32_rna(v.x - h0); sl[1] = tf32_rna(v.y - h1);
            sl[2] = tf32_rna(v.z - h2); sl[3] = tf32_rna(v.w - h3);
        }
    }
    __syncthreads();

    // ---- load A fragments to registers (warp w owns rows w*16..w*16+15)
    uint32_t Ah[8][4], Am[8][4];
    {
        int r0 = (w << 4) + g, r1 = r0 + 8;
#pragma unroll
        for (int ks = 0; ks < 8; ks++) {
            int k0 = ks * 8 + tg, k1 = k0 + 4;
            const float* st = sm + SM_KEYS;
            Ah[ks][0] = __float_as_uint(st[k0 * STGP + r0]);
            Ah[ks][1] = __float_as_uint(st[k0 * STGP + r1]);
            Ah[ks][2] = __float_as_uint(st[k1 * STGP + r0]);
            Ah[ks][3] = __float_as_uint(st[k1 * STGP + r1]);
            Am[ks][0] = __float_as_uint(st[(k0 + 64) * STGP + r0]);
            Am[ks][1] = __float_as_uint(st[(k0 + 64) * STGP + r1]);
            Am[ks][2] = __float_as_uint(st[(k1 + 64) * STGP + r0]);
            Am[ks][3] = __float_as_uint(st[(k1 + 64) * STGP + r1]);
        }
    }
    __syncthreads();   // staging consumed; keys region free for epilogue use

    float worst = -FLT_MAX;
    int wp = 0;
    int rb = (tid & 127) * 21;

    for (int mt = 0; mt < 32; mt++) {
        // ---- selection for previous tile (owners), concurrent with B load
        if (mt > 0 && tid < 128) {
            int m0p = (mt - 1) << 7;
            const float2* krow = (const float2*)(sm + SM_KEYS + tid * KEYP);
#pragma unroll 4
            for (int c2 = 0; c2 < 64; c2++) {
                float2 kk = krow[c2];
                if (kk.x > worst) {
                    sm[SM_RBEST + rb + wp] = kk.x; smi[SM_RIDX + rb + wp] = m0p + 2 * c2;
                    worst = sm[SM_RBEST + rb]; wp = 0;
#pragma unroll
                    for (int t = 1; t < KNN; t++) {
                        float vv = sm[SM_RBEST + rb + t];
                        if (vv < worst) { worst = vv; wp = t; }
                    }
                }
                if (kk.y > worst) {
                    sm[SM_RBEST + rb + wp] = kk.y; smi[SM_RIDX + rb + wp] = m0p + 2 * c2 + 1;
                    worst = sm[SM_RBEST + rb]; wp = 0;
#pragma unroll
                    for (int t = 1; t < KNN; t++) {
                        float vv = sm[SM_RBEST + rb + t];
                        if (vv < worst) { worst = vv; wp = t; }
                    }
                }
            }
        }

        // ---- load + split + permute-store B tile (cols m0..m0+127)
        {
            const float* src = xb + (mt << 7);
#pragma unroll
            for (int it = 0; it < 8; it++) {
                int c = it * 8 + w;
                int nn = lane << 2;
                float4 v = *(const float4*)(src + (size_t)c * NPTS + nn);
                int kstep = c >> 3, kk = c & 7;
                int tig = kk & 3, slot = kk >> 2;
                float hv[4], mv[4];
                hv[0] = tf32_rna(v.x); mv[0] = tf32_rna(v.x - hv[0]);
                hv[1] = tf32_rna(v.y); mv[1] = tf32_rna(v.y - hv[1]);
                hv[2] = tf32_rna(v.z); mv[2] = tf32_rna(v.z - hv[2]);
                hv[3] = tf32_rna(v.w); mv[3] = tf32_rna(v.w - hv[3]);
#pragma unroll
                for (int j = 0; j < 4; j++) {
                    int n = nn + j;
                    int colt = n >> 3, gg = n & 7;
                    int s = (gg << 2) | tig;
                    int idx2 = ((colt << 3) + kstep) * 32 + (s ^ colt);
                    int fo = idx2 * 2 + slot;
                    sm[SM_BPH + fo] = hv[j];
                    sm[SM_BPM + fo] = mv[j];
                }
            }
        }
        __syncthreads();   // B ready (and prev keys consumed)

        // ---- MMA: acc[colt] over 8 ksteps x 3 products
        float acc[16][4];
#pragma unroll
        for (int ct = 0; ct < 16; ct++) {
            acc[ct][0] = 0.f; acc[ct][1] = 0.f; acc[ct][2] = 0.f; acc[ct][3] = 0.f;
        }
#pragma unroll
        for (int ks = 0; ks < 8; ks++) {
#pragma unroll
            for (int ct = 0; ct < 16; ct++) {
                int idx2 = ((ct << 3) + ks) * 32 + (lane ^ ct);
                float2 bh = *(const float2*)(sm + SM_BPH + idx2 * 2);
                float2 bm = *(const float2*)(sm + SM_BPM + idx2 * 2);
                uint32_t bh0 = __float_as_uint(bh.x), bh1 = __float_as_uint(bh.y);
                uint32_t bm0 = __float_as_uint(bm.x), bm1 = __float_as_uint(bm.y);
                mma_tf32(acc[ct], Ah[ks], bh0, bh1);
                mma_tf32(acc[ct], Ah[ks], bm0, bm1);
                mma_tf32(acc[ct], Am[ks], bh0, bh1);
            }
        }

        // ---- epilogue: key = acc - 0.5|x_m|^2 -> keys SMEM
        {
            int m0 = mt << 7;
            int r0 = (w << 4) + g, r1 = r0 + 8;
#pragma unroll
            for (int ct = 0; ct < 16; ct++) {
                int nc = ct * 8 + tg * 2;
                float2 hs = *(const float2*)(sm + SM_HSQ + m0 + nc);
                float2 k01, k23;
                k01.x = acc[ct][0] - hs.x; k01.y = acc[ct][1] - hs.y;
                k23.x = acc[ct][2] - hs.x; k23.y = acc[ct][3] - hs.y;
                *(float2*)(sm + SM_KEYS + r0 * KEYP + nc) = k01;
                *(float2*)(sm + SM_KEYS + r1 * KEYP + nc) = k23;
            }
        }
        __syncthreads();   // keys(mt) ready
    }

    // ---- final tile selection + output
    if (tid < 128) {
        int m0p = 31 << 7;
        const float2* krow = (const float2*)(sm + SM_KEYS + tid * KEYP);
#pragma unroll 4
        for (int c2 = 0; c2 < 64; c2++) {
            float2 kk = krow[c2];
            if (kk.x > worst) {
                sm[SM_RBEST + rb + wp] = kk.x; smi[SM_RIDX + rb + wp] = m0p + 2 * c2;
                worst = sm[SM_RBEST + rb]; wp = 0;
#pragma unroll
                for (int t = 1; t < KNN; t++) {
                    float vv = sm[SM_RBEST + rb + t];
                    if (vv < worst) { worst = vv; wp = t; }
                }
            }
            if (kk.y > worst) {
                sm[SM_RBEST + rb + wp] = kk.y; smi[SM_RIDX + rb + wp] = m0p + 2 * c2 + 1;
                worst = sm[SM_RBEST + rb]; wp = 0;
#pragma unroll
                for (int t = 1; t < KNN; t++) {
                    float vv = sm[SM_RBEST + rb + t];
                    if (vv < worst) { worst = vv; wp = t; }
                }
            }
        }
        int* outp = g_idx + (size_t)((b << 12) + n0 + tid) * KNN;
#pragma unroll
        for (int t = 0; t < KNN; t++) outp[t] = smi[SM_RIDX + rb + t];
    }
}

// ---------------- gather u over neighbors: max/min + BN partials ------------
__global__ void __launch_bounds__(256) gather_kernel() {
    __shared__ float shS[4][OC];
    __shared__ float shQ[4][OC];
    int o = threadIdx.x & 63, p = threadIdx.x >> 6;
    int pt = blockIdx.x * 4 + p;
    int b = pt >> 12;
    const int* idxp = g_idx + (size_t)pt * KNN;
    const float* ub = g_u + ((size_t)(b << 12)) * OC;

    float mx = -FLT_MAX, mn = FLT_MAX, s = 0.f, q = 0.f;
#pragma unroll
    for (int k = 0; k < KNN; k++) {
        int j = idxp[k];
        float uv = ub[(size_t)j * OC + o];
        mx = fmaxf(mx, uv);
        mn = fminf(mn, uv);
        s += uv;
        q = fmaf(uv, uv, q);
    }
    size_t base = (size_t)pt * OC + o;
    float vv = g_v[base];
    g_Mmax[base] = mx;
    g_Mmin[base] = mn;
    shS[p][o] = s + (float)KNN * vv;
    shQ[p][o] = q + 2.f * vv * s + (float)KNN * vv * vv;
    __syncthreads();
    if (p == 0) {
        g_partS[blockIdx.x * OC + o] = shS[0][o] + shS[1][o] + shS[2][o] + shS[3][o];
        g_partQ[blockIdx.x * OC + o] = shQ[0][o] + shQ[1][o] + shQ[2][o] + shQ[3][o];
    }
}

// ---------------- deterministic per-channel reduction ------------------------
__global__ void reduce_kernel() {
    __shared__ float sh[256];
    int o = blockIdx.x & 63;
    bool isQ = (blockIdx.x & 64) != 0;
    const float* src = isQ ? g_partQ : g_partS;
    float s = 0.f;
    for (int i = threadIdx.x; i < 8192; i += 256) s += src[(size_t)i * OC + o];
    sh[threadIdx.x] = s;
    __syncthreads();
    for (int st = 128; st > 0; st >>= 1) {
        if (threadIdx.x < st) sh[threadIdx.x] += sh[threadIdx.x + st];
        __syncthreads();
    }
    if (threadIdx.x == 0) {
        if (isQ) g_sumsq[o] = sh[0]; else g_sum[o] = sh[0];
    }
}

__global__ void finalize_kernel(const float* __restrict__ gamma,
                                const float* __restrict__ beta) {
    int o = threadIdx.x;
    float cnt = (float)((size_t)BATCH * NPTS * KNN);
    float mean = g_sum[o] / cnt;
    float var = g_sumsq[o] / cnt - mean * mean;
    float sc = gamma[o] * rsqrtf(var + BN_EPS);
    g_scale[o] = sc;
    g_shift[o] = beta[o] - mean * sc;
}

// ---------------- output: scale/shift/leaky + transpose to [B, O, N] --------
__global__ void __launch_bounds__(256) out_kernel(float* __restrict__ out) {
    __shared__ float tile[OC][33];
    int b = blockIdx.y;
    int n0 = blockIdx.x * 32;
    for (int t = threadIdx.x; t < OC * 32; t += 256) {
        int nl = t >> 6, o = t & 63;
        size_t base = ((size_t)((b << 12) + n0 + nl)) * OC + o;
        float sc = g_scale[o];
        float m = (sc >= 0.f) ? g_Mmax[base] : g_Mmin[base];
        float y = fmaf(sc, m + g_v[base], g_shift[o]);
        tile[o][nl] = (y >= 0.f) ? y : NEG_SLOPE * y;
    }
    __syncthreads();
    for (int t = threadIdx.x; t < OC * 32; t += 256) {
        int o = t >> 5, nl = t & 31;
        out[((size_t)b * OC + o) * NPTS + n0 + nl] = tile[o][nl];
    }
}

// ---------------- launch ------------------------------------------------------
extern "C" void kernel_launch(void* const* d_in, const int* in_sizes, int n_in,
                              void* d_out, int out_size) {
    const float* x     = (const float*)d_in[0];   // [8, 64, 4096]
    const float* W     = (const float*)d_in[1];   // [64, 128]
    const float* gamma = (const float*)d_in[2];   // [64]
    const float* beta  = (const float*)d_in[3];   // [64]
    float* out = (float*)d_out;                   // [8, 64, 4096]

    cudaFuncSetAttribute(fused_knn_mma,
                         cudaFuncAttributeMaxDynamicSharedMemorySize, SMEM_BYTES);

    sq_kernel<<<NPOINTS / 256, 256>>>(x);
    uv_kernel<<<NPOINTS / 4, 256>>>(x, W);
    fused_knn_mma<<<dim3(NPTS / 128, BATCH), 256, SMEM_BYTES>>>(x);
    gather_kernel<<<NPOINTS / 4, 256>>>();
    reduce_kernel<<<128, 256>>>();
    finalize_kernel<<<1, 64>>>(gamma, beta);
    out_kernel<<<dim3(NPTS / 32, BATCH), 256>>>(out);
}